// round 2
// baseline (speedup 1.0000x reference)
#include <cuda_runtime.h>
#include <cuda_bf16.h>
#include <mma.h>
#include <cstdint>

using namespace nvcuda;

// Problem constants (fixed by the dataset)
#define NB 4
#define NL 1024
#define DM 512            // d_model
#define FD 1024           // d_ffn
#define NE 8              // experts
#define TOPK 2
#define NTOK (NB*NL)      // 4096
#define NSLOT (NTOK*TOPK) // 8192

// ---------------- scratch (static device globals; no allocation) -------------
__device__ __nv_bfloat16 g_xn[NTOK * DM];        // normalized activations, bf16
__device__ __nv_bfloat16 g_H[NSLOT * FD];        // per-slot SwiGLU hidden, bf16
__device__ int   g_topidx[NSLOT];
__device__ float g_topw[NSLOT];
__device__ int   g_cnt[NE];
__device__ int   g_cur[NE];
__device__ int   g_off[NE];
__device__ int   g_top1[NE];
__device__ float g_probsum[NE];
__device__ int   g_perm[NSLOT];                  // slot -> token
__device__ float g_wcomb[NSLOT];                 // slot -> combine weight

// ---------------- K0: zero counters -----------------------------------------
__global__ void k_zero() {
    int t = threadIdx.x;
    if (t < NE) { g_cnt[t] = 0; g_cur[t] = 0; g_top1[t] = 0; g_probsum[t] = 0.f; }
}

// ---------------- K1: RMSNorm + router + residual init -----------------------
// one block (256 threads) per token
__global__ __launch_bounds__(256) void k_norm_router(
    const float* __restrict__ x, const float* __restrict__ norm_w,
    const float* __restrict__ gate_w, float* __restrict__ out)
{
    int token = blockIdx.x;
    int tid   = threadIdx.x;
    __shared__ float s_xn[DM];
    __shared__ float s_red[8];
    __shared__ float s_logit[NE];
    __shared__ float s_prob[NE];

    const float2 v = reinterpret_cast<const float2*>(x + (size_t)token * DM)[tid];
    float ss = v.x * v.x + v.y * v.y;
    #pragma unroll
    for (int o = 16; o; o >>= 1) ss += __shfl_xor_sync(0xffffffffu, ss, o);
    if ((tid & 31) == 0) s_red[tid >> 5] = ss;
    __syncthreads();
    if (tid == 0) {
        float t = 0.f;
        #pragma unroll
        for (int i = 0; i < 8; i++) t += s_red[i];
        s_red[0] = rsqrtf(t / (float)DM + 1e-6f);
    }
    __syncthreads();
    float rstd = s_red[0];
    float2 nw = reinterpret_cast<const float2*>(norm_w)[tid];
    float a0 = v.x * rstd * nw.x;
    float a1 = v.y * rstd * nw.y;
    s_xn[2 * tid]     = a0;
    s_xn[2 * tid + 1] = a1;
    // residual init of output
    reinterpret_cast<float2*>(out + (size_t)token * DM)[tid] = v;
    // bf16 copy for the GEMMs
    reinterpret_cast<__nv_bfloat162*>(g_xn + (size_t)token * DM)[tid] =
        __floats2bfloat162_rn(a0, a1);
    __syncthreads();

    // logits: warp e computes logit_e (8 warps)
    int w = tid >> 5, lane = tid & 31;
    {
        const float* gw = gate_w + w * DM;
        float acc = 0.f;
        #pragma unroll
        for (int j = lane; j < DM; j += 32) acc += s_xn[j] * gw[j];
        #pragma unroll
        for (int o = 16; o; o >>= 1) acc += __shfl_xor_sync(0xffffffffu, acc, o);
        if (lane == 0) s_logit[w] = acc;
    }
    __syncthreads();

    if (tid == 0) {
        float mx = -1e30f;
        #pragma unroll
        for (int e = 0; e < NE; e++) mx = fmaxf(mx, s_logit[e]);
        float p[NE]; float se = 0.f;
        #pragma unroll
        for (int e = 0; e < NE; e++) { p[e] = expf(s_logit[e] - mx); se += p[e]; }
        float inv = 1.f / se;
        int i1 = 0; float p1 = -1.f;
        #pragma unroll
        for (int e = 0; e < NE; e++) {
            p[e] *= inv; s_prob[e] = p[e];
            if (p[e] > p1) { p1 = p[e]; i1 = e; }
        }
        int i2 = 0; float p2 = -1.f;
        #pragma unroll
        for (int e = 0; e < NE; e++)
            if (e != i1 && p[e] > p2) { p2 = p[e]; i2 = e; }
        float sw = p1 + p2; if (sw < 1e-9f) sw = 1e-9f;
        g_topidx[token * 2]     = i1;
        g_topidx[token * 2 + 1] = i2;
        g_topw[token * 2]       = p1 / sw;
        g_topw[token * 2 + 1]   = p2 / sw;
        atomicAdd(&g_cnt[i1], 1);
        atomicAdd(&g_cnt[i2], 1);
        atomicAdd(&g_top1[i1], 1);   // argmax == top-1
    }
    __syncthreads();
    if (tid < NE) atomicAdd(&g_probsum[tid], s_prob[tid]);
}

// ---------------- K2: prefix offsets -----------------------------------------
__global__ void k_offsets() {
    if (threadIdx.x == 0) {
        int a = 0;
        #pragma unroll
        for (int e = 0; e < NE; e++) { g_off[e] = a; a += g_cnt[e]; }
    }
}

// ---------------- K3: build per-expert token lists ----------------------------
__global__ void k_scatter() {
    int t = blockIdx.x * blockDim.x + threadIdx.x;
    if (t >= NTOK) return;
    #pragma unroll
    for (int s = 0; s < TOPK; s++) {
        int e = g_topidx[2 * t + s];
        int p = atomicAdd(&g_cur[e], 1);
        int slot = g_off[e] + p;
        g_perm[slot]  = t;
        g_wcomb[slot] = g_topw[2 * t + s];
    }
}

// ---------------- K4: gathered gate+up GEMM + SwiGLU --------------------------
// grid (FD/64, NTOK/64, NE), block 256 (8 warps). 64x64 output tile, K-step 16.
__global__ __launch_bounds__(256) void k_gateup(
    const float* __restrict__ Wg, const float* __restrict__ Wu)
{
    int e   = blockIdx.z;
    int cnt = g_cnt[e];
    int m0  = blockIdx.y * 64;
    if (m0 >= cnt) return;
    int f0  = blockIdx.x * 64;
    int off = g_off[e];

    __shared__ alignas(16) __nv_bfloat16 sA[64][24];
    __shared__ alignas(16) __nv_bfloat16 sG[64][24];
    __shared__ alignas(16) __nv_bfloat16 sU[64][24];
    __shared__ int   s_row[64];
    __shared__ float sO[64][68];

    int tid = threadIdx.x;
    if (tid < 64) { int r = m0 + tid; s_row[tid] = (r < cnt) ? g_perm[off + r] : -1; }
    __syncthreads();

    int w  = tid >> 5;
    int wr = w >> 1;      // 0..3 : 16-row slice
    int wc = w & 1;       // 0..1 : 32-col slice
    wmma::fragment<wmma::accumulator, 16, 16, 16, float> accG[2], accU[2];
    #pragma unroll
    for (int c = 0; c < 2; c++) { wmma::fill_fragment(accG[c], 0.f); wmma::fill_fragment(accU[c], 0.f); }

    int lr = tid >> 2;          // 0..63 row
    int lc = (tid & 3) * 4;     // 0,4,8,12 within K-step
    const float4* pG = reinterpret_cast<const float4*>(Wg + (size_t)e * FD * DM + (size_t)(f0 + lr) * DM);
    const float4* pU = reinterpret_cast<const float4*>(Wu + (size_t)e * FD * DM + (size_t)(f0 + lr) * DM);
    int arow = s_row[lr];
    const __nv_bfloat16* pA = (arow >= 0) ? (g_xn + (size_t)arow * DM) : nullptr;

    for (int kk = 0; kk < DM; kk += 16) {
        uint2 aval = make_uint2(0u, 0u);
        if (pA) aval = *reinterpret_cast<const uint2*>(pA + kk + lc);
        float4 gv = pG[(kk + lc) >> 2];
        float4 uv = pU[(kk + lc) >> 2];
        __syncthreads();
        *reinterpret_cast<uint2*>(&sA[lr][lc]) = aval;
        {
            __nv_bfloat162* d2 = reinterpret_cast<__nv_bfloat162*>(&sG[lr][lc]);
            d2[0] = __floats2bfloat162_rn(gv.x, gv.y);
            d2[1] = __floats2bfloat162_rn(gv.z, gv.w);
        }
        {
            __nv_bfloat162* d2 = reinterpret_cast<__nv_bfloat162*>(&sU[lr][lc]);
            d2[0] = __floats2bfloat162_rn(uv.x, uv.y);
            d2[1] = __floats2bfloat162_rn(uv.z, uv.w);
        }
        __syncthreads();
        wmma::fragment<wmma::matrix_a, 16, 16, 16, __nv_bfloat16, wmma::row_major> fa;
        wmma::load_matrix_sync(fa, &sA[wr * 16][0], 24);
        #pragma unroll
        for (int c = 0; c < 2; c++) {
            wmma::fragment<wmma::matrix_b, 16, 16, 16, __nv_bfloat16, wmma::col_major> fb;
            wmma::load_matrix_sync(fb, &sG[wc * 32 + c * 16][0], 24);
            wmma::mma_sync(accG[c], fa, fb, accG[c]);
            wmma::load_matrix_sync(fb, &sU[wc * 32 + c * 16][0], 24);
            wmma::mma_sync(accU[c], fa, fb, accU[c]);
        }
    }

    // SwiGLU in-register (acc fragments share layout)
    #pragma unroll
    for (int c = 0; c < 2; c++)
        #pragma unroll
        for (int i = 0; i < accG[c].num_elements; i++) {
            float g = accG[c].x[i], u = accU[c].x[i];
            accG[c].x[i] = (g / (1.f + __expf(-g))) * u;
        }
    #pragma unroll
    for (int c = 0; c < 2; c++)
        wmma::store_matrix_sync(&sO[wr * 16][wc * 32 + c * 16], accG[c], 68, wmma::mem_row_major);
    __syncthreads();

    int lim = cnt - m0; if (lim > 64) lim = 64;
    for (int idx = tid; idx < 64 * 64; idx += 256) {
        int r = idx >> 6, c = idx & 63;
        if (r < lim)
            g_H[(size_t)(off + m0 + r) * FD + f0 + c] = __float2bfloat16(sO[r][c]);
    }
}

// ---------------- K5: down GEMM + weighted scatter-add ------------------------
// grid (DM/64, NTOK/64, NE), block 256.
__global__ __launch_bounds__(256) void k_down(
    const float* __restrict__ Wd, float* __restrict__ out)
{
    int e   = blockIdx.z;
    int cnt = g_cnt[e];
    int m0  = blockIdx.y * 64;
    if (m0 >= cnt) return;
    int d0  = blockIdx.x * 64;
    int off = g_off[e];

    __shared__ alignas(16) __nv_bfloat16 sA[64][24];
    __shared__ alignas(16) __nv_bfloat16 sB[64][24];
    __shared__ float sO[64][68];
    __shared__ int   s_tok[64];
    __shared__ float s_w[64];

    int tid = threadIdx.x;
    int lim = cnt - m0; if (lim > 64) lim = 64;
    if (tid < 64) {
        if (tid < lim) { s_tok[tid] = g_perm[off + m0 + tid]; s_w[tid] = g_wcomb[off + m0 + tid]; }
        else           { s_tok[tid] = -1; s_w[tid] = 0.f; }
    }
    __syncthreads();

    int w  = tid >> 5, wr = w >> 1, wc = w & 1;
    wmma::fragment<wmma::accumulator, 16, 16, 16, float> acc[2];
    #pragma unroll
    for (int c = 0; c < 2; c++) wmma::fill_fragment(acc[c], 0.f);

    int lr = tid >> 2;
    int lc = (tid & 3) * 4;
    bool avalid = lr < lim;
    const __nv_bfloat16* pA = g_H + (size_t)(off + m0 + lr) * FD;
    const float4* pB = reinterpret_cast<const float4*>(Wd + (size_t)e * DM * FD + (size_t)(d0 + lr) * FD);

    for (int kk = 0; kk < FD; kk += 16) {
        uint2 aval = make_uint2(0u, 0u);
        if (avalid) aval = *reinterpret_cast<const uint2*>(pA + kk + lc);
        float4 bv = pB[(kk + lc) >> 2];
        __syncthreads();
        *reinterpret_cast<uint2*>(&sA[lr][lc]) = aval;
        {
            __nv_bfloat162* d2 = reinterpret_cast<__nv_bfloat162*>(&sB[lr][lc]);
            d2[0] = __floats2bfloat162_rn(bv.x, bv.y);
            d2[1] = __floats2bfloat162_rn(bv.z, bv.w);
        }
        __syncthreads();
        wmma::fragment<wmma::matrix_a, 16, 16, 16, __nv_bfloat16, wmma::row_major> fa;
        wmma::load_matrix_sync(fa, &sA[wr * 16][0], 24);
        #pragma unroll
        for (int c = 0; c < 2; c++) {
            wmma::fragment<wmma::matrix_b, 16, 16, 16, __nv_bfloat16, wmma::col_major> fb;
            wmma::load_matrix_sync(fb, &sB[wc * 32 + c * 16][0], 24);
            wmma::mma_sync(acc[c], fa, fb, acc[c]);
        }
    }
    #pragma unroll
    for (int c = 0; c < 2; c++)
        wmma::store_matrix_sync(&sO[wr * 16][wc * 32 + c * 16], acc[c], 68, wmma::mem_row_major);
    __syncthreads();

    for (int idx = tid; idx < 64 * 64; idx += 256) {
        int r = idx >> 6, c = idx & 63;
        if (r < lim) {
            int tok = s_tok[r];
            atomicAdd(&out[(size_t)tok * DM + d0 + c], s_w[r] * sO[r][c]);
        }
    }
}

// ---------------- K6: aux loss ------------------------------------------------
__global__ void k_aux(float* __restrict__ out, int out_size) {
    if (threadIdx.x == 0) {
        float s = 0.f;
        #pragma unroll
        for (int e = 0; e < NE; e++)
            s += ((float)g_top1[e] / (float)NTOK) * (g_probsum[e] / (float)NTOK);
        s *= (float)NE;
        if (out_size > NTOK * DM) out[NTOK * DM] = s;
    }
}

// ---------------- launch ------------------------------------------------------
extern "C" void kernel_launch(void* const* d_in, const int* in_sizes, int n_in,
                              void* d_out, int out_size)
{
    const float* x      = (const float*)d_in[0];
    const float* norm_w = (const float*)d_in[1];
    const float* gate_w = (const float*)d_in[2];
    const float* Wg     = (const float*)d_in[3];
    const float* Wu     = (const float*)d_in[4];
    const float* Wd     = (const float*)d_in[5];
    float* out = (float*)d_out;

    k_zero<<<1, 32>>>();
    k_norm_router<<<NTOK, 256>>>(x, norm_w, gate_w, out);
    k_offsets<<<1, 32>>>();
    k_scatter<<<NTOK / 256, 256>>>();
    k_gateup<<<dim3(FD / 64, NTOK / 64, NE), 256>>>(Wg, Wu);
    k_down<<<dim3(DM / 64, NTOK / 64, NE), 256>>>(Wd, out);
    k_aux<<<1, 32>>>(out, out_size);
}

// round 3
// speedup vs baseline: 1.3016x; 1.3016x over previous
#include <cuda_runtime.h>
#include <cuda_bf16.h>
#include <mma.h>
#include <cstdint>

using namespace nvcuda;

#define DM 512
#define FD 1024
#define NE 8
#define TOPK 2
#define NTOK 4096
#define NSLOT (NTOK*TOPK)

#define BM 128
#define BN 64
#define BK 64
#define LDS 72            // bf16 elements per smem row (64 + 8 pad = 144B, 16B aligned)
#define ASZ (BM*LDS*2)    // 18432
#define GSZ (BN*LDS*2)    // 9216
#define SSZ (ASZ+2*GSZ)   // 36864 per stage
#define SMEM_DYN (2*SSZ)  // 73728

// ---------------- scratch -----------------------------------------------------
__device__ __nv_bfloat16 g_xn[NTOK * DM];
__device__ __nv_bfloat16 g_H[NSLOT * FD];
__device__ __nv_bfloat16 g_Wgb[NE * FD * DM];
__device__ __nv_bfloat16 g_Wub[NE * FD * DM];
__device__ __nv_bfloat16 g_Wdb[NE * DM * FD];
__device__ int   g_topidx[NSLOT];
__device__ float g_topw[NSLOT];
__device__ int   g_cnt[NE];
__device__ int   g_off[NE];
__device__ int   g_top1[NE];
__device__ float g_probsum[NE];
__device__ int   g_perm[NSLOT];
__device__ float g_wcomb[NSLOT];

// ---------------- cp.async helpers -------------------------------------------
__device__ __forceinline__ void cp16(uint32_t dst, const void* src) {
    asm volatile("cp.async.cg.shared.global [%0], [%1], 16;\n" :: "r"(dst), "l"(src));
}
__device__ __forceinline__ void cp_commit() {
    asm volatile("cp.async.commit_group;\n");
}

// ---------------- K: weight fp32 -> bf16 --------------------------------------
__global__ __launch_bounds__(256) void k_convert(
    const float* __restrict__ Wg, const float* __restrict__ Wu,
    const float* __restrict__ Wd)
{
    const float* src; __nv_bfloat16* dst;
    if (blockIdx.y == 0)      { src = Wg; dst = g_Wgb; }
    else if (blockIdx.y == 1) { src = Wu; dst = g_Wub; }
    else                      { src = Wd; dst = g_Wdb; }
    size_t i = ((size_t)blockIdx.x * 256 + threadIdx.x) * 4;
    float4 v = *reinterpret_cast<const float4*>(src + i);
    __nv_bfloat162* d2 = reinterpret_cast<__nv_bfloat162*>(dst + i);
    d2[0] = __floats2bfloat162_rn(v.x, v.y);
    d2[1] = __floats2bfloat162_rn(v.z, v.w);
}

// ---------------- K: zero counters --------------------------------------------
__global__ void k_zero() {
    int t = threadIdx.x;
    if (t < NE) { g_cnt[t] = 0; g_top1[t] = 0; g_probsum[t] = 0.f; }
}

// ---------------- K: RMSNorm + router + residual init --------------------------
__global__ __launch_bounds__(256) void k_norm_router(
    const float* __restrict__ x, const float* __restrict__ norm_w,
    const float* __restrict__ gate_w, float* __restrict__ out)
{
    int token = blockIdx.x;
    int tid   = threadIdx.x;
    __shared__ float s_xn[DM];
    __shared__ float s_red[8];
    __shared__ float s_logit[NE];
    __shared__ float s_prob[NE];

    const float2 v = reinterpret_cast<const float2*>(x + (size_t)token * DM)[tid];
    float ss = v.x * v.x + v.y * v.y;
    #pragma unroll
    for (int o = 16; o; o >>= 1) ss += __shfl_xor_sync(0xffffffffu, ss, o);
    if ((tid & 31) == 0) s_red[tid >> 5] = ss;
    __syncthreads();
    if (tid == 0) {
        float t = 0.f;
        #pragma unroll
        for (int i = 0; i < 8; i++) t += s_red[i];
        s_red[0] = rsqrtf(t / (float)DM + 1e-6f);
    }
    __syncthreads();
    float rstd = s_red[0];
    float2 nw = reinterpret_cast<const float2*>(norm_w)[tid];
    float a0 = v.x * rstd * nw.x;
    float a1 = v.y * rstd * nw.y;
    s_xn[2 * tid]     = a0;
    s_xn[2 * tid + 1] = a1;
    reinterpret_cast<float2*>(out + (size_t)token * DM)[tid] = v;   // residual
    reinterpret_cast<__nv_bfloat162*>(g_xn + (size_t)token * DM)[tid] =
        __floats2bfloat162_rn(a0, a1);
    __syncthreads();

    int w = tid >> 5, lane = tid & 31;
    {
        const float* gw = gate_w + w * DM;
        float acc = 0.f;
        #pragma unroll
        for (int j = lane; j < DM; j += 32) acc += s_xn[j] * gw[j];
        #pragma unroll
        for (int o = 16; o; o >>= 1) acc += __shfl_xor_sync(0xffffffffu, acc, o);
        if (lane == 0) s_logit[w] = acc;
    }
    __syncthreads();

    if (tid == 0) {
        float mx = -1e30f;
        #pragma unroll
        for (int e = 0; e < NE; e++) mx = fmaxf(mx, s_logit[e]);
        float p[NE]; float se = 0.f;
        #pragma unroll
        for (int e = 0; e < NE; e++) { p[e] = expf(s_logit[e] - mx); se += p[e]; }
        float inv = 1.f / se;
        int i1 = 0; float p1 = -1.f;
        #pragma unroll
        for (int e = 0; e < NE; e++) {
            p[e] *= inv; s_prob[e] = p[e];
            if (p[e] > p1) { p1 = p[e]; i1 = e; }
        }
        int i2 = 0; float p2 = -1.f;
        #pragma unroll
        for (int e = 0; e < NE; e++)
            if (e != i1 && p[e] > p2) { p2 = p[e]; i2 = e; }
        float sw = p1 + p2; if (sw < 1e-9f) sw = 1e-9f;
        g_topidx[token * 2]     = i1;
        g_topidx[token * 2 + 1] = i2;
        g_topw[token * 2]       = p1 / sw;
        g_topw[token * 2 + 1]   = p2 / sw;
        atomicAdd(&g_cnt[i1], 1);
        atomicAdd(&g_cnt[i2], 1);
        atomicAdd(&g_top1[i1], 1);
    }
    __syncthreads();
    if (tid < NE) atomicAdd(&g_probsum[tid], s_prob[tid]);
}

// ---------------- K: fused prefix-offsets + scatter (single block) -------------
__global__ __launch_bounds__(1024) void k_off_scatter() {
    __shared__ int s_cur[NE];
    int t = threadIdx.x;
    if (t < NE) s_cur[t] = 0;
    if (t == 0) {
        int a = 0;
        #pragma unroll
        for (int e = 0; e < NE; e++) { g_off[e] = a; a += g_cnt[e]; }
    }
    __syncthreads();
    for (int tok = t; tok < NTOK; tok += 1024) {
        #pragma unroll
        for (int s = 0; s < TOPK; s++) {
            int e = g_topidx[2 * tok + s];
            int p = atomicAdd(&s_cur[e], 1);
            int slot = g_off[e] + p;
            g_perm[slot]  = tok;
            g_wcomb[slot] = g_topw[2 * tok + s];
        }
    }
}

// ---------------- K: gate+up GEMM + SwiGLU (128x64 tiles, double-buffered) -----
__global__ __launch_bounds__(256) void k_gateup()
{
    int e   = blockIdx.z;
    int cnt = g_cnt[e];
    int m0  = blockIdx.y * BM;
    if (m0 >= cnt) return;
    int f0  = blockIdx.x * BN;
    int off = g_off[e];

    extern __shared__ char smem[];
    __shared__ int s_row[BM];

    int t = threadIdx.x;
    if (t < BM) { int r = m0 + t; s_row[t] = (r < cnt) ? g_perm[off + r] : 0; }
    __syncthreads();

    // per-thread load descriptors
    const __nv_bfloat16* a_src[4];
    uint32_t a_dst[4];
    uint32_t sbase = (uint32_t)__cvta_generic_to_shared(smem);
    #pragma unroll
    for (int j = 0; j < 4; j++) {
        int u = t * 4 + j;                 // 0..1023
        int row = u >> 3, q = u & 7;
        a_src[j] = g_xn + (size_t)s_row[row] * DM + q * 8;
        a_dst[j] = sbase + row * (LDS * 2) + q * 16;
    }
    const __nv_bfloat16* g_src[2]; const __nv_bfloat16* u_src[2];
    uint32_t gu_dst[2];
    #pragma unroll
    for (int j = 0; j < 2; j++) {
        int u = t * 2 + j;                 // 0..511
        int row = u >> 3, q = u & 7;
        g_src[j] = g_Wgb + ((size_t)e * FD + f0 + row) * DM + q * 8;
        u_src[j] = g_Wub + ((size_t)e * FD + f0 + row) * DM + q * 8;
        gu_dst[j] = sbase + row * (LDS * 2) + q * 16;
    }

    auto issue = [&](int k0, int st) {
        uint32_t so = st * SSZ;
        #pragma unroll
        for (int j = 0; j < 4; j++) cp16(a_dst[j] + so, a_src[j] + k0);
        #pragma unroll
        for (int j = 0; j < 2; j++) {
            cp16(gu_dst[j] + so + ASZ,       g_src[j] + k0);
            cp16(gu_dst[j] + so + ASZ + GSZ, u_src[j] + k0);
        }
    };

    int w  = t >> 5;
    int wr = w >> 1;      // 0..3 -> 32-row slice
    int wc = w & 1;       // 0..1 -> 32-col slice

    wmma::fragment<wmma::accumulator, 16, 16, 16, float> accG[2][2], accU[2][2];
    #pragma unroll
    for (int i = 0; i < 2; i++)
        #pragma unroll
        for (int j = 0; j < 2; j++) {
            wmma::fill_fragment(accG[i][j], 0.f);
            wmma::fill_fragment(accU[i][j], 0.f);
        }

    issue(0, 0);
    cp_commit();

    const int nk = DM / BK;   // 8
    for (int c = 0; c < nk; c++) {
        int st = c & 1;
        if (c + 1 < nk) {
            issue((c + 1) * BK, st ^ 1);
            cp_commit();
            asm volatile("cp.async.wait_group 1;\n");
        } else {
            asm volatile("cp.async.wait_group 0;\n");
        }
        __syncthreads();

        const __nv_bfloat16* pA = (const __nv_bfloat16*)(smem + st * SSZ);
        const __nv_bfloat16* pG = (const __nv_bfloat16*)(smem + st * SSZ + ASZ);
        const __nv_bfloat16* pU = (const __nv_bfloat16*)(smem + st * SSZ + ASZ + GSZ);

        #pragma unroll
        for (int ks = 0; ks < BK / 16; ks++) {
            wmma::fragment<wmma::matrix_a, 16, 16, 16, __nv_bfloat16, wmma::row_major> fa[2];
            wmma::fragment<wmma::matrix_b, 16, 16, 16, __nv_bfloat16, wmma::col_major> fg[2], fu[2];
            #pragma unroll
            for (int i = 0; i < 2; i++)
                wmma::load_matrix_sync(fa[i], pA + (wr * 32 + i * 16) * LDS + ks * 16, LDS);
            #pragma unroll
            for (int j = 0; j < 2; j++) {
                wmma::load_matrix_sync(fg[j], pG + (wc * 32 + j * 16) * LDS + ks * 16, LDS);
                wmma::load_matrix_sync(fu[j], pU + (wc * 32 + j * 16) * LDS + ks * 16, LDS);
            }
            #pragma unroll
            for (int i = 0; i < 2; i++)
                #pragma unroll
                for (int j = 0; j < 2; j++) {
                    wmma::mma_sync(accG[i][j], fa[i], fg[j], accG[i][j]);
                    wmma::mma_sync(accU[i][j], fa[i], fu[j], accU[i][j]);
                }
        }
        __syncthreads();
    }

    // SwiGLU in-register
    #pragma unroll
    for (int i = 0; i < 2; i++)
        #pragma unroll
        for (int j = 0; j < 2; j++)
            #pragma unroll
            for (int k = 0; k < accG[i][j].num_elements; k++) {
                float g = accG[i][j].x[k], uu = accU[i][j].x[k];
                accG[i][j].x[k] = (g / (1.f + __expf(-g))) * uu;
            }

    float* sO = (float*)smem;  // 128 x 68 fp32 = 34816 B, fits in dyn smem
    #pragma unroll
    for (int i = 0; i < 2; i++)
        #pragma unroll
        for (int j = 0; j < 2; j++)
            wmma::store_matrix_sync(sO + (wr * 32 + i * 16) * 68 + wc * 32 + j * 16,
                                    accG[i][j], 68, wmma::mem_row_major);
    __syncthreads();

    int lim = cnt - m0; if (lim > BM) lim = BM;
    for (int u = t; u < BM * BN; u += 256) {
        int r = u >> 6, cc = u & 63;
        if (r < lim)
            g_H[(size_t)(off + m0 + r) * FD + f0 + cc] = __float2bfloat16(sO[r * 68 + cc]);
    }
}

// ---------------- K: down GEMM + weighted scatter-add --------------------------
__global__ __launch_bounds__(256) void k_down(float* __restrict__ out)
{
    int e   = blockIdx.z;
    int cnt = g_cnt[e];
    int m0  = blockIdx.y * BM;
    if (m0 >= cnt) return;
    int d0  = blockIdx.x * BN;
    int off = g_off[e];

    extern __shared__ char smem[];
    __shared__ int   s_tok[BM];
    __shared__ float s_w[BM];

    int t = threadIdx.x;
    int lim = cnt - m0; if (lim > BM) lim = BM;
    if (t < BM) {
        if (t < lim) { s_tok[t] = g_perm[off + m0 + t]; s_w[t] = g_wcomb[off + m0 + t]; }
        else         { s_tok[t] = 0; s_w[t] = 0.f; }
    }
    __syncthreads();

    uint32_t sbase = (uint32_t)__cvta_generic_to_shared(smem);
    const __nv_bfloat16* a_src[4];
    uint32_t a_dst[4];
    #pragma unroll
    for (int j = 0; j < 4; j++) {
        int u = t * 4 + j;
        int row = u >> 3, q = u & 7;
        int gr = off + m0 + row; if (gr >= NSLOT) gr = 0;
        a_src[j] = g_H + (size_t)gr * FD + q * 8;
        a_dst[j] = sbase + row * (LDS * 2) + q * 16;
    }
    const __nv_bfloat16* b_src[2];
    uint32_t b_dst[2];
    #pragma unroll
    for (int j = 0; j < 2; j++) {
        int u = t * 2 + j;
        int row = u >> 3, q = u & 7;
        b_src[j] = g_Wdb + ((size_t)e * DM + d0 + row) * FD + q * 8;
        b_dst[j] = sbase + row * (LDS * 2) + q * 16;
    }

    auto issue = [&](int k0, int st) {
        uint32_t so = st * SSZ;
        #pragma unroll
        for (int j = 0; j < 4; j++) cp16(a_dst[j] + so, a_src[j] + k0);
        #pragma unroll
        for (int j = 0; j < 2; j++) cp16(b_dst[j] + so + ASZ, b_src[j] + k0);
    };

    int w  = t >> 5;
    int wr = w >> 1;
    int wc = w & 1;

    wmma::fragment<wmma::accumulator, 16, 16, 16, float> acc[2][2];
    #pragma unroll
    for (int i = 0; i < 2; i++)
        #pragma unroll
        for (int j = 0; j < 2; j++) wmma::fill_fragment(acc[i][j], 0.f);

    issue(0, 0);
    cp_commit();

    const int nk = FD / BK;   // 16
    for (int c = 0; c < nk; c++) {
        int st = c & 1;
        if (c + 1 < nk) {
            issue((c + 1) * BK, st ^ 1);
            cp_commit();
            asm volatile("cp.async.wait_group 1;\n");
        } else {
            asm volatile("cp.async.wait_group 0;\n");
        }
        __syncthreads();

        const __nv_bfloat16* pA = (const __nv_bfloat16*)(smem + st * SSZ);
        const __nv_bfloat16* pB = (const __nv_bfloat16*)(smem + st * SSZ + ASZ);

        #pragma unroll
        for (int ks = 0; ks < BK / 16; ks++) {
            wmma::fragment<wmma::matrix_a, 16, 16, 16, __nv_bfloat16, wmma::row_major> fa[2];
            wmma::fragment<wmma::matrix_b, 16, 16, 16, __nv_bfloat16, wmma::col_major> fb[2];
            #pragma unroll
            for (int i = 0; i < 2; i++)
                wmma::load_matrix_sync(fa[i], pA + (wr * 32 + i * 16) * LDS + ks * 16, LDS);
            #pragma unroll
            for (int j = 0; j < 2; j++)
                wmma::load_matrix_sync(fb[j], pB + (wc * 32 + j * 16) * LDS + ks * 16, LDS);
            #pragma unroll
            for (int i = 0; i < 2; i++)
                #pragma unroll
                for (int j = 0; j < 2; j++)
                    wmma::mma_sync(acc[i][j], fa[i], fb[j], acc[i][j]);
        }
        __syncthreads();
    }

    float* sO = (float*)smem;
    #pragma unroll
    for (int i = 0; i < 2; i++)
        #pragma unroll
        for (int j = 0; j < 2; j++)
            wmma::store_matrix_sync(sO + (wr * 32 + i * 16) * 68 + wc * 32 + j * 16,
                                    acc[i][j], 68, wmma::mem_row_major);
    __syncthreads();

    for (int u = t; u < BM * BN; u += 256) {
        int r = u >> 6, cc = u & 63;
        if (r < lim)
            atomicAdd(&out[(size_t)s_tok[r] * DM + d0 + cc], s_w[r] * sO[r * 68 + cc]);
    }
}

// ---------------- K: aux loss --------------------------------------------------
__global__ void k_aux(float* __restrict__ out, int out_size) {
    if (threadIdx.x == 0) {
        float s = 0.f;
        #pragma unroll
        for (int e = 0; e < NE; e++)
            s += ((float)g_top1[e] / (float)NTOK) * (g_probsum[e] / (float)NTOK);
        s *= (float)NE;
        if (out_size > NTOK * DM) out[NTOK * DM] = s;
    }
}

// ---------------- launch --------------------------------------------------------
extern "C" void kernel_launch(void* const* d_in, const int* in_sizes, int n_in,
                              void* d_out, int out_size)
{
    const float* x      = (const float*)d_in[0];
    const float* norm_w = (const float*)d_in[1];
    const float* gate_w = (const float*)d_in[2];
    const float* Wg     = (const float*)d_in[3];
    const float* Wu     = (const float*)d_in[4];
    const float* Wd     = (const float*)d_in[5];
    float* out = (float*)d_out;

    cudaFuncSetAttribute(k_gateup, cudaFuncAttributeMaxDynamicSharedMemorySize, SMEM_DYN);
    cudaFuncSetAttribute(k_down,   cudaFuncAttributeMaxDynamicSharedMemorySize, SMEM_DYN);

    k_convert<<<dim3(NE * FD * DM / 4 / 256, 3), 256>>>(Wg, Wu, Wd);
    k_zero<<<1, 32>>>();
    k_norm_router<<<NTOK, 256>>>(x, norm_w, gate_w, out);
    k_off_scatter<<<1, 1024>>>();
    k_gateup<<<dim3(FD / BN, NTOK / BM, NE), 256, SMEM_DYN>>>();
    k_down<<<dim3(DM / BN, NTOK / BM, NE), 256, SMEM_DYN>>>(out);
    k_aux<<<1, 32>>>(out, out_size);
}

// round 4
// speedup vs baseline: 1.3766x; 1.0576x over previous
#include <cuda_runtime.h>
#include <cuda_bf16.h>
#include <mma.h>
#include <cstdint>

using namespace nvcuda;

#define DM 512
#define FD 1024
#define NE 8
#define TOPK 2
#define NTOK 4096
#define NSLOT (NTOK*TOPK)

#define BM 128
#define BN 64
#define BK 64
#define LDS 72            // bf16 elements per smem row (64 + 8 pad = 144B, 16B aligned)
#define ASZ (BM*LDS*2)    // 18432
#define GSZ (BN*LDS*2)    // 9216
#define SSZ (ASZ+2*GSZ)   // 36864 per stage
#define SMEM_DYN (2*SSZ)  // 73728

// ---------------- scratch -----------------------------------------------------
__device__ __nv_bfloat16 g_xn[NTOK * DM];
__device__ __nv_bfloat16 g_H[NSLOT * FD];
__device__ __nv_bfloat16 g_Wgb[NE * FD * DM];
__device__ __nv_bfloat16 g_Wub[NE * FD * DM];
__device__ __nv_bfloat16 g_Wdb[NE * DM * FD];
__device__ int   g_topidx[NSLOT];
__device__ float g_topw[NSLOT];
__device__ int   g_cnt[NE];
__device__ int   g_off[NE];
__device__ int   g_top1[NE];
__device__ float g_probsum[NE];
__device__ int   g_perm[NSLOT];
__device__ float g_wcomb[NSLOT];

// ---------------- cp.async helpers -------------------------------------------
__device__ __forceinline__ void cp16(uint32_t dst, const void* src) {
    asm volatile("cp.async.cg.shared.global [%0], [%1], 16;\n" :: "r"(dst), "l"(src));
}
__device__ __forceinline__ void cp_commit() {
    asm volatile("cp.async.commit_group;\n");
}

// ---------------- K: weight fp32 -> bf16 --------------------------------------
__global__ __launch_bounds__(256) void k_convert(
    const float* __restrict__ Wg, const float* __restrict__ Wu,
    const float* __restrict__ Wd)
{
    const float* src; __nv_bfloat16* dst;
    if (blockIdx.y == 0)      { src = Wg; dst = g_Wgb; }
    else if (blockIdx.y == 1) { src = Wu; dst = g_Wub; }
    else                      { src = Wd; dst = g_Wdb; }
    size_t i = ((size_t)blockIdx.x * 256 + threadIdx.x) * 4;
    float4 v = *reinterpret_cast<const float4*>(src + i);
    __nv_bfloat162* d2 = reinterpret_cast<__nv_bfloat162*>(dst + i);
    d2[0] = __floats2bfloat162_rn(v.x, v.y);
    d2[1] = __floats2bfloat162_rn(v.z, v.w);
}

// ---------------- K: zero counters --------------------------------------------
__global__ void k_zero() {
    int t = threadIdx.x;
    if (t < NE) { g_cnt[t] = 0; g_top1[t] = 0; g_probsum[t] = 0.f; }
}

// ---------------- K: RMSNorm + router + residual init --------------------------
__global__ __launch_bounds__(256) void k_norm_router(
    const float* __restrict__ x, const float* __restrict__ norm_w,
    const float* __restrict__ gate_w, float* __restrict__ out)
{
    int token = blockIdx.x;
    int tid   = threadIdx.x;
    __shared__ float s_xn[DM];
    __shared__ float s_red[8];
    __shared__ float s_logit[NE];
    __shared__ float s_prob[NE];

    const float2 v = reinterpret_cast<const float2*>(x + (size_t)token * DM)[tid];
    float ss = v.x * v.x + v.y * v.y;
    #pragma unroll
    for (int o = 16; o; o >>= 1) ss += __shfl_xor_sync(0xffffffffu, ss, o);
    if ((tid & 31) == 0) s_red[tid >> 5] = ss;
    __syncthreads();
    if (tid == 0) {
        float t = 0.f;
        #pragma unroll
        for (int i = 0; i < 8; i++) t += s_red[i];
        s_red[0] = rsqrtf(t / (float)DM + 1e-6f);
    }
    __syncthreads();
    float rstd = s_red[0];
    float2 nw = reinterpret_cast<const float2*>(norm_w)[tid];
    float a0 = v.x * rstd * nw.x;
    float a1 = v.y * rstd * nw.y;
    s_xn[2 * tid]     = a0;
    s_xn[2 * tid + 1] = a1;
    reinterpret_cast<float2*>(out + (size_t)token * DM)[tid] = v;   // residual
    reinterpret_cast<__nv_bfloat162*>(g_xn + (size_t)token * DM)[tid] =
        __floats2bfloat162_rn(a0, a1);
    __syncthreads();

    int w = tid >> 5, lane = tid & 31;
    {
        const float* gw = gate_w + w * DM;
        float acc = 0.f;
        #pragma unroll
        for (int j = lane; j < DM; j += 32) acc += s_xn[j] * gw[j];
        #pragma unroll
        for (int o = 16; o; o >>= 1) acc += __shfl_xor_sync(0xffffffffu, acc, o);
        if (lane == 0) s_logit[w] = acc;
    }
    __syncthreads();

    if (tid == 0) {
        float mx = -1e30f;
        #pragma unroll
        for (int e = 0; e < NE; e++) mx = fmaxf(mx, s_logit[e]);
        float p[NE]; float se = 0.f;
        #pragma unroll
        for (int e = 0; e < NE; e++) { p[e] = expf(s_logit[e] - mx); se += p[e]; }
        float inv = 1.f / se;
        int i1 = 0; float p1 = -1.f;
        #pragma unroll
        for (int e = 0; e < NE; e++) {
            p[e] *= inv; s_prob[e] = p[e];
            if (p[e] > p1) { p1 = p[e]; i1 = e; }
        }
        int i2 = 0; float p2 = -1.f;
        #pragma unroll
        for (int e = 0; e < NE; e++)
            if (e != i1 && p[e] > p2) { p2 = p[e]; i2 = e; }
        float sw = p1 + p2; if (sw < 1e-9f) sw = 1e-9f;
        g_topidx[token * 2]     = i1;
        g_topidx[token * 2 + 1] = i2;
        g_topw[token * 2]       = p1 / sw;
        g_topw[token * 2 + 1]   = p2 / sw;
        atomicAdd(&g_cnt[i1], 1);
        atomicAdd(&g_cnt[i2], 1);
        atomicAdd(&g_top1[i1], 1);
    }
    __syncthreads();
    if (tid < NE) atomicAdd(&g_probsum[tid], s_prob[tid]);
}

// ---------------- K: fused prefix-offsets + scatter (single block) -------------
__global__ __launch_bounds__(1024) void k_off_scatter() {
    __shared__ int s_cur[NE];
    int t = threadIdx.x;
    if (t < NE) s_cur[t] = 0;
    if (t == 0) {
        int a = 0;
        #pragma unroll
        for (int e = 0; e < NE; e++) { g_off[e] = a; a += g_cnt[e]; }
    }
    __syncthreads();
    for (int tok = t; tok < NTOK; tok += 1024) {
        #pragma unroll
        for (int s = 0; s < TOPK; s++) {
            int e = g_topidx[2 * tok + s];
            int p = atomicAdd(&s_cur[e], 1);
            int slot = g_off[e] + p;
            g_perm[slot]  = tok;
            g_wcomb[slot] = g_topw[2 * tok + s];
        }
    }
}

// ---------------- K: gate+up GEMM + SwiGLU (128x64 tiles, double-buffered) -----
__global__ __launch_bounds__(256) void k_gateup()
{
    int e   = blockIdx.z;
    int cnt = g_cnt[e];
    int m0  = blockIdx.y * BM;
    if (m0 >= cnt) return;
    int f0  = blockIdx.x * BN;
    int off = g_off[e];

    extern __shared__ char smem[];
    __shared__ int s_row[BM];

    int t = threadIdx.x;
    if (t < BM) { int r = m0 + t; s_row[t] = (r < cnt) ? g_perm[off + r] : 0; }
    __syncthreads();

    // per-thread load descriptors
    const __nv_bfloat16* a_src[4];
    uint32_t a_dst[4];
    uint32_t sbase = (uint32_t)__cvta_generic_to_shared(smem);
    #pragma unroll
    for (int j = 0; j < 4; j++) {
        int u = t * 4 + j;                 // 0..1023
        int row = u >> 3, q = u & 7;
        a_src[j] = g_xn + (size_t)s_row[row] * DM + q * 8;
        a_dst[j] = sbase + row * (LDS * 2) + q * 16;
    }
    const __nv_bfloat16* g_src[2]; const __nv_bfloat16* u_src[2];
    uint32_t gu_dst[2];
    #pragma unroll
    for (int j = 0; j < 2; j++) {
        int u = t * 2 + j;                 // 0..511
        int row = u >> 3, q = u & 7;
        g_src[j] = g_Wgb + ((size_t)e * FD + f0 + row) * DM + q * 8;
        u_src[j] = g_Wub + ((size_t)e * FD + f0 + row) * DM + q * 8;
        gu_dst[j] = sbase + row * (LDS * 2) + q * 16;
    }

    auto issue = [&](int k0, int st) {
        uint32_t so = st * SSZ;
        #pragma unroll
        for (int j = 0; j < 4; j++) cp16(a_dst[j] + so, a_src[j] + k0);
        #pragma unroll
        for (int j = 0; j < 2; j++) {
            cp16(gu_dst[j] + so + ASZ,       g_src[j] + k0);
            cp16(gu_dst[j] + so + ASZ + GSZ, u_src[j] + k0);
        }
    };

    int w  = t >> 5;
    int wr = w >> 1;      // 0..3 -> 32-row slice
    int wc = w & 1;       // 0..1 -> 32-col slice

    wmma::fragment<wmma::accumulator, 16, 16, 16, float> accG[2][2], accU[2][2];
    #pragma unroll
    for (int i = 0; i < 2; i++)
        #pragma unroll
        for (int j = 0; j < 2; j++) {
            wmma::fill_fragment(accG[i][j], 0.f);
            wmma::fill_fragment(accU[i][j], 0.f);
        }

    issue(0, 0);
    cp_commit();

    const int nk = DM / BK;   // 8
    for (int c = 0; c < nk; c++) {
        int st = c & 1;
        if (c + 1 < nk) {
            issue((c + 1) * BK, st ^ 1);
            cp_commit();
            asm volatile("cp.async.wait_group 1;\n");
        } else {
            asm volatile("cp.async.wait_group 0;\n");
        }
        __syncthreads();

        const __nv_bfloat16* pA = (const __nv_bfloat16*)(smem + st * SSZ);
        const __nv_bfloat16* pG = (const __nv_bfloat16*)(smem + st * SSZ + ASZ);
        const __nv_bfloat16* pU = (const __nv_bfloat16*)(smem + st * SSZ + ASZ + GSZ);

        #pragma unroll
        for (int ks = 0; ks < BK / 16; ks++) {
            wmma::fragment<wmma::matrix_a, 16, 16, 16, __nv_bfloat16, wmma::row_major> fa[2];
            wmma::fragment<wmma::matrix_b, 16, 16, 16, __nv_bfloat16, wmma::col_major> fg[2], fu[2];
            #pragma unroll
            for (int i = 0; i < 2; i++)
                wmma::load_matrix_sync(fa[i], pA + (wr * 32 + i * 16) * LDS + ks * 16, LDS);
            #pragma unroll
            for (int j = 0; j < 2; j++) {
                wmma::load_matrix_sync(fg[j], pG + (wc * 32 + j * 16) * LDS + ks * 16, LDS);
                wmma::load_matrix_sync(fu[j], pU + (wc * 32 + j * 16) * LDS + ks * 16, LDS);
            }
            #pragma unroll
            for (int i = 0; i < 2; i++)
                #pragma unroll
                for (int j = 0; j < 2; j++) {
                    wmma::mma_sync(accG[i][j], fa[i], fg[j], accG[i][j]);
                    wmma::mma_sync(accU[i][j], fa[i], fu[j], accU[i][j]);
                }
        }
        __syncthreads();
    }

    // SwiGLU in-register
    #pragma unroll
    for (int i = 0; i < 2; i++)
        #pragma unroll
        for (int j = 0; j < 2; j++)
            #pragma unroll
            for (int k = 0; k < accG[i][j].num_elements; k++) {
                float g = accG[i][j].x[k], uu = accU[i][j].x[k];
                accG[i][j].x[k] = (g / (1.f + __expf(-g))) * uu;
            }

    float* sO = (float*)smem;  // 128 x 68 fp32 = 34816 B, fits in dyn smem
    #pragma unroll
    for (int i = 0; i < 2; i++)
        #pragma unroll
        for (int j = 0; j < 2; j++)
            wmma::store_matrix_sync(sO + (wr * 32 + i * 16) * 68 + wc * 32 + j * 16,
                                    accG[i][j], 68, wmma::mem_row_major);
    __syncthreads();

    int lim = cnt - m0; if (lim > BM) lim = BM;
    for (int u = t; u < BM * BN; u += 256) {
        int r = u >> 6, cc = u & 63;
        if (r < lim)
            g_H[(size_t)(off + m0 + r) * FD + f0 + cc] = __float2bfloat16(sO[r * 68 + cc]);
    }
}

// ---------------- K: down GEMM + weighted scatter-add --------------------------
__global__ __launch_bounds__(256) void k_down(float* __restrict__ out)
{
    int e   = blockIdx.z;
    int cnt = g_cnt[e];
    int m0  = blockIdx.y * BM;
    if (m0 >= cnt) return;
    int d0  = blockIdx.x * BN;
    int off = g_off[e];

    extern __shared__ char smem[];
    __shared__ int   s_tok[BM];
    __shared__ float s_w[BM];

    int t = threadIdx.x;
    int lim = cnt - m0; if (lim > BM) lim = BM;
    if (t < BM) {
        if (t < lim) { s_tok[t] = g_perm[off + m0 + t]; s_w[t] = g_wcomb[off + m0 + t]; }
        else         { s_tok[t] = 0; s_w[t] = 0.f; }
    }
    __syncthreads();

    uint32_t sbase = (uint32_t)__cvta_generic_to_shared(smem);
    const __nv_bfloat16* a_src[4];
    uint32_t a_dst[4];
    #pragma unroll
    for (int j = 0; j < 4; j++) {
        int u = t * 4 + j;
        int row = u >> 3, q = u & 7;
        int gr = off + m0 + row; if (gr >= NSLOT) gr = 0;
        a_src[j] = g_H + (size_t)gr * FD + q * 8;
        a_dst[j] = sbase + row * (LDS * 2) + q * 16;
    }
    const __nv_bfloat16* b_src[2];
    uint32_t b_dst[2];
    #pragma unroll
    for (int j = 0; j < 2; j++) {
        int u = t * 2 + j;
        int row = u >> 3, q = u & 7;
        b_src[j] = g_Wdb + ((size_t)e * DM + d0 + row) * FD + q * 8;
        b_dst[j] = sbase + row * (LDS * 2) + q * 16;
    }

    auto issue = [&](int k0, int st) {
        uint32_t so = st * SSZ;
        #pragma unroll
        for (int j = 0; j < 4; j++) cp16(a_dst[j] + so, a_src[j] + k0);
        #pragma unroll
        for (int j = 0; j < 2; j++) cp16(b_dst[j] + so + ASZ, b_src[j] + k0);
    };

    int w  = t >> 5;
    int wr = w >> 1;
    int wc = w & 1;

    wmma::fragment<wmma::accumulator, 16, 16, 16, float> acc[2][2];
    #pragma unroll
    for (int i = 0; i < 2; i++)
        #pragma unroll
        for (int j = 0; j < 2; j++) wmma::fill_fragment(acc[i][j], 0.f);

    issue(0, 0);
    cp_commit();

    const int nk = FD / BK;   // 16
    for (int c = 0; c < nk; c++) {
        int st = c & 1;
        if (c + 1 < nk) {
            issue((c + 1) * BK, st ^ 1);
            cp_commit();
            asm volatile("cp.async.wait_group 1;\n");
        } else {
            asm volatile("cp.async.wait_group 0;\n");
        }
        __syncthreads();

        const __nv_bfloat16* pA = (const __nv_bfloat16*)(smem + st * SSZ);
        const __nv_bfloat16* pB = (const __nv_bfloat16*)(smem + st * SSZ + ASZ);

        #pragma unroll
        for (int ks = 0; ks < BK / 16; ks++) {
            wmma::fragment<wmma::matrix_a, 16, 16, 16, __nv_bfloat16, wmma::row_major> fa[2];
            wmma::fragment<wmma::matrix_b, 16, 16, 16, __nv_bfloat16, wmma::col_major> fb[2];
            #pragma unroll
            for (int i = 0; i < 2; i++)
                wmma::load_matrix_sync(fa[i], pA + (wr * 32 + i * 16) * LDS + ks * 16, LDS);
            #pragma unroll
            for (int j = 0; j < 2; j++)
                wmma::load_matrix_sync(fb[j], pB + (wc * 32 + j * 16) * LDS + ks * 16, LDS);
            #pragma unroll
            for (int i = 0; i < 2; i++)
                #pragma unroll
                for (int j = 0; j < 2; j++)
                    wmma::mma_sync(acc[i][j], fa[i], fb[j], acc[i][j]);
        }
        __syncthreads();
    }

    float* sO = (float*)smem;
    #pragma unroll
    for (int i = 0; i < 2; i++)
        #pragma unroll
        for (int j = 0; j < 2; j++)
            wmma::store_matrix_sync(sO + (wr * 32 + i * 16) * 68 + wc * 32 + j * 16,
                                    acc[i][j], 68, wmma::mem_row_major);
    __syncthreads();

    for (int u = t; u < BM * BN; u += 256) {
        int r = u >> 6, cc = u & 63;
        if (r < lim)
            atomicAdd(&out[(size_t)s_tok[r] * DM + d0 + cc], s_w[r] * sO[r * 68 + cc]);
    }
}

// ---------------- K: aux loss --------------------------------------------------
__global__ void k_aux(float* __restrict__ out, int out_size) {
    if (threadIdx.x == 0) {
        float s = 0.f;
        #pragma unroll
        for (int e = 0; e < NE; e++)
            s += ((float)g_top1[e] / (float)NTOK) * (g_probsum[e] / (float)NTOK);
        s *= (float)NE;
        if (out_size > NTOK * DM) out[NTOK * DM] = s;
    }
}

// ---------------- launch --------------------------------------------------------
extern "C" void kernel_launch(void* const* d_in, const int* in_sizes, int n_in,
                              void* d_out, int out_size)
{
    const float* x      = (const float*)d_in[0];
    const float* norm_w = (const float*)d_in[1];
    const float* gate_w = (const float*)d_in[2];
    const float* Wg     = (const float*)d_in[3];
    const float* Wu     = (const float*)d_in[4];
    const float* Wd     = (const float*)d_in[5];
    float* out = (float*)d_out;

    cudaFuncSetAttribute(k_gateup, cudaFuncAttributeMaxDynamicSharedMemorySize, SMEM_DYN);
    cudaFuncSetAttribute(k_down,   cudaFuncAttributeMaxDynamicSharedMemorySize, SMEM_DYN);

    k_convert<<<dim3(NE * FD * DM / 4 / 256, 3), 256>>>(Wg, Wu, Wd);
    k_zero<<<1, 32>>>();
    k_norm_router<<<NTOK, 256>>>(x, norm_w, gate_w, out);
    k_off_scatter<<<1, 1024>>>();
    k_gateup<<<dim3(FD / BN, NTOK / BM, NE), 256, SMEM_DYN>>>();
    k_down<<<dim3(DM / BN, NTOK / BM, NE), 256, SMEM_DYN>>>(out);
    k_aux<<<1, 32>>>(out, out_size);
}